// round 8
// baseline (speedup 1.0000x reference)
#include <cuda_runtime.h>
#include <cstdint>

// Problem constants
namespace {
constexpr int kB   = 16;
constexpr int kN   = 2048;
constexpr int kD   = 128;
constexpr int kOpe = 64;
constexpr int BE   = 128;          // e-rows per attention CTA
constexpr int BL   = 64;           // l-cols per tile
constexpr int NT   = kN / BL;      // 32 tiles

// attention smem layout (float offsets)
constexpr int RS_OFF = 0;                    // rowsum[128]
constexpr int Q_OFF  = 128;                  // Q tf32 bits [128][132]
constexpr int K_OFF  = Q_OFF + 128 * 132;    // K tf32 bits [64][132]
constexpr int P_OFF  = K_OFF + 64 * 132;     // P tf32 bits [128][68]
constexpr int VT_OFF = P_OFF + 128 * 68;     // V^T tf32 bits [128][68]
constexpr int ATTN_FLOATS = VT_OFF + 128 * 68;   // 42880 floats = 171520 B

// proj smem layout (float offsets)
constexpr int PH_OFF = 0;                    // H tf32 bits [128][132]; reused as out-stage
constexpr int PW_OFF = 128 * 132;            // W^T tf32 bits [128][132]
constexpr int PS_OFF = PW_OFF + 128 * 132;   // scale[128]
constexpr int PROJ_FLOATS = PS_OFF + 128;    // 33920 floats = 135680 B
}

// Scratch (allocation-free rule: __device__ globals). All tf32-rounded bits.
__device__ float g_q[kB * kN * kD];
__device__ float g_k[kB * kN * kD];          // (h@Wk) * a_w / sqrt(d) folded in
__device__ float g_vt[kB * kD * kN];         // V transposed: [b][d][token]
__device__ float g_gate[kB * kN * kD];

// ---------------------------------------------------------------------------
// PTX helpers
// ---------------------------------------------------------------------------
__device__ __forceinline__ uint32_t smem_u32(const void* p) {
    uint32_t a;
    asm("{ .reg .u64 t; cvta.to.shared.u64 t, %1; cvt.u32.u64 %0, t; }"
        : "=r"(a) : "l"(p));
    return a;
}
__device__ __forceinline__ uint32_t f2tf32(float f) {
    uint32_t u;
    asm("cvt.rna.tf32.f32 %0, %1;" : "=r"(u) : "f"(f));
    return u;
}
// C += A(16x8) * B(8x8), tf32 inputs, fp32 accum
__device__ __forceinline__ void mma_tf32(float* c, const uint32_t* a,
                                         uint32_t b0, uint32_t b1) {
    asm volatile(
        "mma.sync.aligned.m16n8k8.row.col.f32.tf32.tf32.f32 "
        "{%0,%1,%2,%3}, {%4,%5,%6,%7}, {%8,%9}, {%0,%1,%2,%3};"
        : "+f"(c[0]), "+f"(c[1]), "+f"(c[2]), "+f"(c[3])
        : "r"(a[0]), "r"(a[1]), "r"(a[2]), "r"(a[3]), "r"(b0), "r"(b1));
}
__device__ __forceinline__ void cp16(uint32_t dst, const float* src) {
    asm volatile("cp.async.cg.shared.global [%0], [%1], 16;"
                 :: "r"(dst), "l"(src) : "memory");
}
#define CP_COMMIT() asm volatile("cp.async.commit_group;" ::: "memory")
#define CP_WAIT1()  asm volatile("cp.async.wait_group 1;" ::: "memory")

// ---------------------------------------------------------------------------
// QKV projection via tf32 mma.sync: out = h @ W (which: 0=Q,1=K,2=V).
// K gets a_w/sqrt(d) folded in. Outputs stored as tf32-rounded bits.
// V is written transposed to g_vt[b][d][token].
// Block: 256 thr, 8 warps 4(M)x2(N), tile 128 tokens x 128 outputs.
// ---------------------------------------------------------------------------
__global__ void __launch_bounds__(256, 1) proj_kernel(
    const float* __restrict__ h,
    const float* __restrict__ Wq,
    const float* __restrict__ Wk,
    const float* __restrict__ Wv,
    const float* __restrict__ a_w)
{
    extern __shared__ float sh[];
    uint32_t* const shu = reinterpret_cast<uint32_t*>(sh);
    const int tid  = threadIdx.x;
    const int lane = tid & 31, wid = tid >> 5;
    const int g    = lane >> 2, tig = lane & 3;
    const int wm   = wid & 3,  wn  = wid >> 2;
    const int which = blockIdx.y;
    const float* __restrict__ W = (which == 0) ? Wq : (which == 1) ? Wk : Wv;
    const int row0 = blockIdx.x * 128;

    // Stage H (tf32 bits), stride 132
    {
        const float* __restrict__ hb = h + (size_t)row0 * kD;
        for (int i = 0; i < 16; i++) {
            const int idx = tid + 256 * i;
            const int r = idx >> 5, c4 = (idx & 31) << 2;
            const float4 v = *reinterpret_cast<const float4*>(&hb[r * kD + c4]);
            uint32_t* dst = &shu[PH_OFF + r * 132 + c4];
            dst[0] = f2tf32(v.x); dst[1] = f2tf32(v.y);
            dst[2] = f2tf32(v.z); dst[3] = f2tf32(v.w);
        }
    }
    // Stage W transposed: WT[n][k] (tf32 bits), stride 132
    for (int idx = tid; idx < 128 * 128; idx += 256) {
        const int k = idx >> 7, n = idx & 127;
        shu[PW_OFF + n * 132 + k] = f2tf32(W[idx]);
    }
    if (tid < 128)
        sh[PS_OFF + tid] = (which == 1) ? a_w[tid] * rsqrtf((float)kD) : 1.0f;
    __syncthreads();

    float o[2][8][4];
#pragma unroll
    for (int mt = 0; mt < 2; mt++)
#pragma unroll
        for (int nt = 0; nt < 8; nt++)
#pragma unroll
            for (int q = 0; q < 4; q++) o[mt][nt][q] = 0.f;

#pragma unroll
    for (int ks = 0; ks < 16; ks++) {
        uint32_t a[2][4];
#pragma unroll
        for (int mt = 0; mt < 2; mt++) {
            const int base = PH_OFF + (wm * 32 + mt * 16 + g) * 132 + ks * 8 + tig;
            a[mt][0] = shu[base];
            a[mt][1] = shu[base + 8 * 132];
            a[mt][2] = shu[base + 4];
            a[mt][3] = shu[base + 8 * 132 + 4];
        }
#pragma unroll
        for (int nt = 0; nt < 8; nt++) {
            const int bb = PW_OFF + (wn * 64 + nt * 8 + g) * 132 + ks * 8 + tig;
            const uint32_t b0 = shu[bb], b1 = shu[bb + 4];
            mma_tf32(o[0][nt], a[0], b0, b1);
            mma_tf32(o[1][nt], a[1], b0, b1);
        }
    }
    __syncthreads();   // H/W reads done; PH region reusable as stage

    if (which < 2) {
        // Scale (K only), round, stage stride 132, then coalesced float4 out
        float* __restrict__ outp = (which == 0) ? g_q : g_k;
#pragma unroll
        for (int mt = 0; mt < 2; mt++)
#pragma unroll
            for (int dd = 0; dd < 2; dd++) {
                const int r = wm * 32 + mt * 16 + g + 8 * dd;
#pragma unroll
                for (int nt = 0; nt < 8; nt++) {
                    const int c0 = wn * 64 + nt * 8 + 2 * tig;
                    const float cs0 = sh[PS_OFF + c0], cs1 = sh[PS_OFF + c0 + 1];
                    const uint32_t p0 = f2tf32(o[mt][nt][2 * dd] * cs0);
                    const uint32_t p1 = f2tf32(o[mt][nt][2 * dd + 1] * cs1);
                    *reinterpret_cast<uint2*>(&shu[PH_OFF + r * 132 + c0]) =
                        make_uint2(p0, p1);
                }
            }
        __syncthreads();
        for (int i = 0; i < 16; i++) {
            const int idx = tid + 256 * i;
            const int r = idx >> 5, c4 = (idx & 31) << 2;
            *reinterpret_cast<float4*>(&outp[(size_t)(row0 + r) * kD + c4]) =
                *reinterpret_cast<const float4*>(&sh[PH_OFF + r * 132 + c4]);
        }
    } else {
        // V: round, stage stride 129 (scalar), then transposed write to g_vt
#pragma unroll
        for (int mt = 0; mt < 2; mt++)
#pragma unroll
            for (int dd = 0; dd < 2; dd++) {
                const int r = wm * 32 + mt * 16 + g + 8 * dd;
#pragma unroll
                for (int nt = 0; nt < 8; nt++) {
                    const int c0 = wn * 64 + nt * 8 + 2 * tig;
                    shu[PH_OFF + r * 129 + c0]     = f2tf32(o[mt][nt][2 * dd]);
                    shu[PH_OFF + r * 129 + c0 + 1] = f2tf32(o[mt][nt][2 * dd + 1]);
                }
            }
        __syncthreads();
        const int bb2 = row0 >> 11;            // batch
        const int t0  = row0 & 2047;           // token offset within batch
#pragma unroll 4
        for (int dloc = 0; dloc < 16; dloc++) {
            const int d = wid * 16 + dloc;
            float4 v;
            v.x = sh[PH_OFF + (lane * 4 + 0) * 129 + d];
            v.y = sh[PH_OFF + (lane * 4 + 1) * 129 + d];
            v.z = sh[PH_OFF + (lane * 4 + 2) * 129 + d];
            v.w = sh[PH_OFF + (lane * 4 + 3) * 129 + d];
            *reinterpret_cast<float4*>(
                &g_vt[((size_t)bb2 * kD + d) * kN + t0 + lane * 4]) = v;
        }
    }
}

// ---------------------------------------------------------------------------
// Gate: sigmoid(op_emb @ op_W + op_b) (unchanged, known-good, ~8us)
// ---------------------------------------------------------------------------
struct GateSmem {
    float W[64][129];
    float E[64][65];
    float bias[128];
};

__global__ void __launch_bounds__(256) gate_kernel(
    const float* __restrict__ op_emb,
    const float* __restrict__ op_W,
    const float* __restrict__ op_b)
{
    extern __shared__ char raw[];
    GateSmem& sm = *reinterpret_cast<GateSmem*>(raw);
    const int tid = threadIdx.x;
    const int row0 = blockIdx.x * 64;

    for (int i = tid; i < 64 * 128; i += 256) sm.W[i >> 7][i & 127] = op_W[i];
    for (int i = tid; i < 64 * 64; i += 256)
        sm.E[i >> 6][i & 63] = op_emb[(size_t)row0 * kOpe + i];
    if (tid < 128) sm.bias[tid] = op_b[tid];
    __syncthreads();

    const int tx = tid & 15, ty = tid >> 4;
    float acc[4][8];
#pragma unroll
    for (int i = 0; i < 4; i++)
#pragma unroll
        for (int j = 0; j < 8; j++) acc[i][j] = 0.f;

    const float* er[4];
#pragma unroll
    for (int i = 0; i < 4; i++) er[i] = sm.E[ty + 16 * i];

#pragma unroll 4
    for (int k = 0; k < 64; k++) {
        float a[4], b[8];
#pragma unroll
        for (int i = 0; i < 4; i++) a[i] = er[i][k];
#pragma unroll
        for (int j = 0; j < 8; j++) b[j] = sm.W[k][tx + 16 * j];
#pragma unroll
        for (int i = 0; i < 4; i++)
#pragma unroll
            for (int j = 0; j < 8; j++) acc[i][j] += a[i] * b[j];
    }

    float bb[8];
#pragma unroll
    for (int j = 0; j < 8; j++) bb[j] = sm.bias[tx + 16 * j];
    __syncthreads();
    float (*stage)[128] = reinterpret_cast<float(*)[128]>(raw);
#pragma unroll
    for (int i = 0; i < 4; i++)
#pragma unroll
        for (int j = 0; j < 8; j++) {
            float v = acc[i][j] + bb[j];
            stage[ty + 16 * i][tx + 16 * j] = 1.f / (1.f + __expf(-v));
        }
    __syncthreads();
    for (int i = tid; i < 64 * 128; i += 256)
        g_gate[(size_t)row0 * kD + i] = stage[i >> 7][i & 127];
}

// ---------------------------------------------------------------------------
// mma.sync tf32 flash attention, cp.async pipelined.
//   All operands pre-rounded tf32 bits in gmem -> raw 16B async copies.
//   Per tile: [VT(t) copies fly over adj prefetch + MMA1]
//             [K(t+1) copies fly over exp + MMA2]
// 8 warps 4(M)x2(N). MMA1: 128x64; MMA2: 128x128.
// ---------------------------------------------------------------------------
__global__ void __launch_bounds__(256, 1) attn_kernel(
    const float* __restrict__ adj,
    const float* __restrict__ ln_g,
    const float* __restrict__ ln_b,
    float* __restrict__ out)
{
    extern __shared__ float sh[];
    uint32_t* const shu = reinterpret_cast<uint32_t*>(sh);
    const uint32_t sb = smem_u32(sh);
    const int tid  = threadIdx.x;
    const int lane = tid & 31, wid = tid >> 5;
    const int g    = lane >> 2, tig = lane & 3;
    const int wm   = wid & 3,  wn  = wid >> 2;
    const int b    = blockIdx.y;
    const int e0   = blockIdx.x * BE;

    // Prologue: async-copy Q (group 0) and K tile 0 (group 1)
    {
        const float* __restrict__ qb = g_q + ((size_t)b * kN + e0) * kD;
#pragma unroll
        for (int i = 0; i < 16; i++) {
            const int idx = tid + 256 * i;
            const int r = idx >> 5, c4 = (idx & 31) << 2;
            cp16(sb + (Q_OFF + r * 132 + c4) * 4, qb + r * kD + c4);
        }
        CP_COMMIT();
        const float* __restrict__ kb = g_k + (size_t)b * kN * kD;
#pragma unroll
        for (int i = 0; i < 8; i++) {
            const int idx = tid + 256 * i;
            const int r = idx >> 5, c4 = (idx & 31) << 2;
            cp16(sb + (K_OFF + r * 132 + c4) * 4, kb + r * kD + c4);
        }
        CP_COMMIT();
    }
    if (tid < 128) sh[RS_OFF + tid] = 0.f;

    float o[2][8][4];
#pragma unroll
    for (int mt = 0; mt < 2; mt++)
#pragma unroll
        for (int nt = 0; nt < 8; nt++)
#pragma unroll
            for (int q = 0; q < 4; q++) o[mt][nt][q] = 0.f;
    float rsum[2][2] = {{0.f, 0.f}, {0.f, 0.f}};

    const float* __restrict__ vt_base = g_vt + (size_t)b * kD * kN;
    const float* __restrict__ k_base  = g_k + (size_t)b * kN * kD;

    for (int lt = 0; lt < NT; lt++) {
        __syncthreads();   // A: prev MMA2 done -> VT, P buffers free

        // VT(t) async copy (in flight until pre-MMA2 wait)
        {
            const float* __restrict__ vtb = vt_base + lt * BL;
#pragma unroll
            for (int i = 0; i < 8; i++) {
                const int idx = tid + 256 * i;
                const int d = idx >> 4, c4 = (idx & 15) << 2;
                cp16(sb + (VT_OFF + d * 68 + c4) * 4, vtb + (size_t)d * kN + c4);
            }
            CP_COMMIT();
        }

        // adj tile prefetch -> registers (streaming)
        float2 adjv[2][2][4];
        {
            const float* __restrict__ ab =
                adj + ((size_t)b * kN + e0) * kN + (size_t)lt * BL;
#pragma unroll
            for (int mt = 0; mt < 2; mt++)
#pragma unroll
                for (int dd = 0; dd < 2; dd++) {
                    const int r = wm * 32 + mt * 16 + g + 8 * dd;
                    const float* ap = ab + (size_t)r * kN + wn * 32 + 2 * tig;
#pragma unroll
                    for (int nt = 0; nt < 4; nt++)
                        adjv[mt][dd][nt] =
                            __ldcs(reinterpret_cast<const float2*>(ap + nt * 8));
                }
        }

        CP_WAIT1();        // K(t) (and Q on first iter) arrived
        __syncthreads();   // B: everyone's K copies visible

        // MMA1: S = Q K^T  (128 x 64)
        float s[2][4][4];
#pragma unroll
        for (int mt = 0; mt < 2; mt++)
#pragma unroll
            for (int nt = 0; nt < 4; nt++)
#pragma unroll
                for (int q = 0; q < 4; q++) s[mt][nt][q] = 0.f;
#pragma unroll
        for (int ks = 0; ks < 16; ks++) {
            uint32_t a[2][4];
#pragma unroll
            for (int mt = 0; mt < 2; mt++) {
                const int base = Q_OFF + (wm * 32 + mt * 16 + g) * 132 + ks * 8 + tig;
                a[mt][0] = shu[base];
                a[mt][1] = shu[base + 8 * 132];
                a[mt][2] = shu[base + 4];
                a[mt][3] = shu[base + 8 * 132 + 4];
            }
#pragma unroll
            for (int nt = 0; nt < 4; nt++) {
                const int bb = K_OFF + (wn * 32 + nt * 8 + g) * 132 + ks * 8 + tig;
                const uint32_t b0 = shu[bb], b1 = shu[bb + 4];
                mma_tf32(s[0][nt], a[0], b0, b1);
                mma_tf32(s[1][nt], a[1], b0, b1);
            }
        }
        __syncthreads();   // C: K buffer free

        // K(t+1) async copy (in flight over exp + MMA2)
        {
            const int tn = (lt + 1) & (NT - 1);
            const float* __restrict__ kbn = k_base + (size_t)tn * BL * kD;
#pragma unroll
            for (int i = 0; i < 8; i++) {
                const int idx = tid + 256 * i;
                const int r = idx >> 5, c4 = (idx & 31) << 2;
                cp16(sb + (K_OFF + r * 132 + c4) * 4, kbn + r * kD + c4);
            }
            CP_COMMIT();
        }

        // P = exp(leaky(S) * adj) -> P buffer (tf32 bits); rowsum in regs
#pragma unroll
        for (int mt = 0; mt < 2; mt++)
#pragma unroll
            for (int dd = 0; dd < 2; dd++) {
                const int r = wm * 32 + mt * 16 + g + 8 * dd;
#pragma unroll
                for (int nt = 0; nt < 4; nt++) {
                    float v0 = s[mt][nt][2 * dd + 0];
                    float v1 = s[mt][nt][2 * dd + 1];
                    v0 = (v0 > 0.f) ? v0 : 0.2f * v0;
                    v1 = (v1 > 0.f) ? v1 : 0.2f * v1;
                    const float2 av = adjv[mt][dd][nt];
                    const uint32_t p0 = f2tf32(__expf(v0 * av.x));
                    const uint32_t p1 = f2tf32(__expf(v1 * av.y));
                    rsum[mt][dd] += __uint_as_float(p0) + __uint_as_float(p1);
                    const int c0 = wn * 32 + nt * 8 + 2 * tig;
                    *reinterpret_cast<uint2*>(&shu[P_OFF + r * 68 + c0]) =
                        make_uint2(p0, p1);
                }
            }

        CP_WAIT1();        // VT(t) arrived
        __syncthreads();   // D: P + everyone's VT visible

        // MMA2: O += P V^T  (128 x 128)
#pragma unroll
        for (int ks = 0; ks < 8; ks++) {
            uint32_t a[2][4];
#pragma unroll
            for (int mt = 0; mt < 2; mt++) {
                const int base = P_OFF + (wm * 32 + mt * 16 + g) * 68 + ks * 8 + tig;
                a[mt][0] = shu[base];
                a[mt][1] = shu[base + 8 * 68];
                a[mt][2] = shu[base + 4];
                a[mt][3] = shu[base + 8 * 68 + 4];
            }
#pragma unroll
            for (int nt = 0; nt < 8; nt++) {
                const int bb = VT_OFF + (wn * 64 + nt * 8 + g) * 68 + ks * 8 + tig;
                const uint32_t b0 = shu[bb], b1 = shu[bb + 4];
                mma_tf32(o[0][nt], a[0], b0, b1);
                mma_tf32(o[1][nt], a[1], b0, b1);
            }
        }
    }

    __syncthreads();
    // Rowsum reduction: 4 lanes (tig) share each row; wn pair via atomicAdd
#pragma unroll
    for (int mt = 0; mt < 2; mt++)
#pragma unroll
        for (int dd = 0; dd < 2; dd++) {
            float v = rsum[mt][dd];
            v += __shfl_xor_sync(0xffffffffu, v, 1);
            v += __shfl_xor_sync(0xffffffffu, v, 2);
            if (tig == 0)
                atomicAdd(&sh[RS_OFF + wm * 32 + mt * 16 + g + 8 * dd], v);
        }
    // Stage O (fp32) into the dead Q buffer (stride 132)
#pragma unroll
    for (int mt = 0; mt < 2; mt++)
#pragma unroll
        for (int dd = 0; dd < 2; dd++) {
            const int r = wm * 32 + mt * 16 + g + 8 * dd;
#pragma unroll
            for (int nt = 0; nt < 8; nt++) {
                const int c0 = wn * 64 + nt * 8 + 2 * tig;
                *reinterpret_cast<float2*>(&sh[Q_OFF + r * 132 + c0]) =
                    make_float2(o[mt][nt][2 * dd], o[mt][nt][2 * dd + 1]);
            }
        }
    __syncthreads();

    // Fused /rowsum + gate + LayerNorm epilogue: warp per 16 rows, float4
    const float4 lg = *reinterpret_cast<const float4*>(&ln_g[lane * 4]);
    const float4 lb = *reinterpret_cast<const float4*>(&ln_b[lane * 4]);
#pragma unroll 2
    for (int rr = 0; rr < 16; rr++) {
        const int r = wid * 16 + rr;
        const float inv = 1.f / sh[RS_OFF + r];
        const float4 ov = *reinterpret_cast<float4*>(&sh[Q_OFF + r * 132 + lane * 4]);
        const size_t gidx = ((size_t)b * kN + e0 + r) * kD + lane * 4;
        const float4 gv = *reinterpret_cast<const float4*>(&g_gate[gidx]);
        const float h0 = ov.x * inv * gv.x, h1 = ov.y * inv * gv.y;
        const float h2 = ov.z * inv * gv.z, h3 = ov.w * inv * gv.w;
        float sum = h0 + h1 + h2 + h3;
#pragma unroll
        for (int off = 16; off; off >>= 1) sum += __shfl_xor_sync(0xffffffffu, sum, off);
        const float mu = sum * (1.f / 128.f);
        const float d0 = h0 - mu, d1 = h1 - mu, d2 = h2 - mu, d3 = h3 - mu;
        float vs = d0 * d0 + d1 * d1 + d2 * d2 + d3 * d3;
#pragma unroll
        for (int off = 16; off; off >>= 1) vs += __shfl_xor_sync(0xffffffffu, vs, off);
        const float rstd = rsqrtf(vs * (1.f / 128.f) + 1e-5f);
        float4 res;
        res.x = d0 * rstd * lg.x + lb.x;
        res.y = d1 * rstd * lg.y + lb.y;
        res.z = d2 * rstd * lg.z + lb.z;
        res.w = d3 * rstd * lg.w + lb.w;
        *reinterpret_cast<float4*>(&out[gidx]) = res;
    }
}

// ---------------------------------------------------------------------------
// Launch
// ---------------------------------------------------------------------------
extern "C" void kernel_launch(void* const* d_in, const int* in_sizes, int n_in,
                              void* d_out, int out_size)
{
    const float* h    = (const float*)d_in[0];
    const float* adj  = (const float*)d_in[1];
    const float* op_e = (const float*)d_in[2];
    const float* Wk   = (const float*)d_in[3];
    const float* Wq   = (const float*)d_in[4];
    const float* Wv   = (const float*)d_in[5];
    const float* a_w  = (const float*)d_in[6];
    const float* op_W = (const float*)d_in[7];
    const float* op_b = (const float*)d_in[8];
    const float* ln_g = (const float*)d_in[9];
    const float* ln_b = (const float*)d_in[10];
    float* out = (float*)d_out;

    cudaFuncSetAttribute(proj_kernel, cudaFuncAttributeMaxDynamicSharedMemorySize,
                         (int)(PROJ_FLOATS * sizeof(float)));
    cudaFuncSetAttribute(gate_kernel, cudaFuncAttributeMaxDynamicSharedMemorySize,
                         (int)sizeof(GateSmem));
    cudaFuncSetAttribute(attn_kernel, cudaFuncAttributeMaxDynamicSharedMemorySize,
                         (int)(ATTN_FLOATS * sizeof(float)));

    proj_kernel<<<dim3((kB * kN) / 128, 3), 256, PROJ_FLOATS * sizeof(float)>>>(
        h, Wq, Wk, Wv, a_w);
    gate_kernel<<<(kB * kN) / 64, 256, sizeof(GateSmem)>>>(op_e, op_W, op_b);
    attn_kernel<<<dim3(kN / BE, kB), 256, ATTN_FLOATS * sizeof(float)>>>(
        adj, ln_g, ln_b, out);
}

// round 9
// speedup vs baseline: 1.6628x; 1.6628x over previous
#include <cuda_runtime.h>
#include <cuda_fp16.h>
#include <cstdint>

// Problem constants
namespace {
constexpr int kB   = 16;
constexpr int kN   = 2048;
constexpr int kD   = 128;
constexpr int kOpe = 64;
constexpr int BE   = 128;          // e-rows per attention CTA
constexpr int BL   = 64;           // l-cols per tile
constexpr int NT   = kN / BL;      // 32 tiles

// attention smem byte offsets (half rows stride 136 halves = 272 B = 17x16B)
constexpr int RS_B = 0;                       // rowsum[128] f32
constexpr int QB   = 512;                     // Q fp16 [128][136]
constexpr int K0B  = QB  + 128 * 272;         // K fp16 [64][136] buf0
constexpr int K1B  = K0B + 64 * 272;          // K buf1
constexpr int VB   = K1B + 64 * 272;          // V fp16 [64][136]
constexpr int PB   = VB  + 64 * 272;          // P fp16 [128][72]
constexpr int ATTN_BYTES = PB + 128 * 144;    // 105984

// proj smem byte offsets
constexpr int HB   = 0;                       // H fp16 [128][136]; reused as out stage
constexpr int WB   = 128 * 272;               // W fp16 [128][136] (natural [k][n])
constexpr int SC_B = WB + 128 * 272;          // scale[128] f32
constexpr int PROJ_BYTES = SC_B + 512;        // 70144
}

// Scratch (allocation-free rule: __device__ globals), fp16
__device__ __half g_q[kB * kN * kD];
__device__ __half g_k[kB * kN * kD];     // (h@Wk) * a_w / sqrt(d) folded in
__device__ __half g_v[kB * kN * kD];
__device__ float  g_gate[kB * kN * kD];

// ---------------------------------------------------------------------------
// PTX helpers
// ---------------------------------------------------------------------------
__device__ __forceinline__ uint32_t smem_u32(const void* p) {
    uint32_t a;
    asm("{ .reg .u64 t; cvta.to.shared.u64 t, %1; cvt.u32.u64 %0, t; }"
        : "=r"(a) : "l"(p));
    return a;
}
__device__ __forceinline__ void ldsm4(uint32_t& r0, uint32_t& r1, uint32_t& r2,
                                      uint32_t& r3, uint32_t addr) {
    asm volatile("ldmatrix.sync.aligned.m8n8.x4.shared.b16 {%0,%1,%2,%3}, [%4];"
                 : "=r"(r0), "=r"(r1), "=r"(r2), "=r"(r3) : "r"(addr));
}
__device__ __forceinline__ void ldsm4t(uint32_t& r0, uint32_t& r1, uint32_t& r2,
                                       uint32_t& r3, uint32_t addr) {
    asm volatile("ldmatrix.sync.aligned.m8n8.x4.trans.shared.b16 {%0,%1,%2,%3}, [%4];"
                 : "=r"(r0), "=r"(r1), "=r"(r2), "=r"(r3) : "r"(addr));
}
// C += A(16x16) * B(16x8), fp16 inputs, fp32 accum
__device__ __forceinline__ void mma_f16(float* c, const uint32_t* a,
                                        uint32_t b0, uint32_t b1) {
    asm volatile(
        "mma.sync.aligned.m16n8k16.row.col.f32.f16.f16.f32 "
        "{%0,%1,%2,%3}, {%4,%5,%6,%7}, {%8,%9}, {%0,%1,%2,%3};"
        : "+f"(c[0]), "+f"(c[1]), "+f"(c[2]), "+f"(c[3])
        : "r"(a[0]), "r"(a[1]), "r"(a[2]), "r"(a[3]), "r"(b0), "r"(b1));
}
__device__ __forceinline__ void cp16(uint32_t dst, const void* src) {
    asm volatile("cp.async.cg.shared.global [%0], [%1], 16;"
                 :: "r"(dst), "l"(src) : "memory");
}
#define CP_COMMIT() asm volatile("cp.async.commit_group;" ::: "memory")
#define CP_WAIT1()  asm volatile("cp.async.wait_group 1;" ::: "memory")
#define CP_WAIT0()  asm volatile("cp.async.wait_group 0;" ::: "memory")

// ---------------------------------------------------------------------------
// QKV projection via fp16 mma: out = h @ W (which: 0=Q,1=K,2=V), fp16 out.
// K gets a_w/sqrt(d) folded in (applied in fp32 before rounding).
// W consumed in natural [k][n] layout via ldmatrix.trans. 8 warps 4(M)x2(N).
// ---------------------------------------------------------------------------
__global__ void __launch_bounds__(256, 2) proj_kernel(
    const float* __restrict__ h,
    const float* __restrict__ Wq,
    const float* __restrict__ Wk,
    const float* __restrict__ Wv,
    const float* __restrict__ a_w)
{
    extern __shared__ char smc[];
    float* const shf = reinterpret_cast<float*>(smc);
    const uint32_t sb = smem_u32(smc);
    const int tid  = threadIdx.x;
    const int lane = tid & 31, wid = tid >> 5;
    const int g    = lane >> 2, tig = lane & 3;
    const int wm   = wid & 3,  wn  = wid >> 2;
    const int which = blockIdx.y;
    const float* __restrict__ W = (which == 0) ? Wq : (which == 1) ? Wk : Wv;
    __half* __restrict__ outp = (which == 0) ? g_q : (which == 1) ? g_k : g_v;
    const int row0 = blockIdx.x * 128;

    // Stage H and W as fp16 (stride 136 halves)
    {
        const float* __restrict__ hb = h + (size_t)row0 * kD;
#pragma unroll
        for (int i = 0; i < 16; i++) {
            const int idx = tid + 256 * i;
            const int r = idx >> 5, c4 = (idx & 31) << 2;
            const float4 v = *reinterpret_cast<const float4*>(&hb[r * kD + c4]);
            *reinterpret_cast<__half2*>(smc + HB + (r * 136 + c4) * 2) =
                __floats2half2_rn(v.x, v.y);
            *reinterpret_cast<__half2*>(smc + HB + (r * 136 + c4) * 2 + 4) =
                __floats2half2_rn(v.z, v.w);
            const float4 w = *reinterpret_cast<const float4*>(&W[r * kD + c4]);
            *reinterpret_cast<__half2*>(smc + WB + (r * 136 + c4) * 2) =
                __floats2half2_rn(w.x, w.y);
            *reinterpret_cast<__half2*>(smc + WB + (r * 136 + c4) * 2 + 4) =
                __floats2half2_rn(w.z, w.w);
        }
    }
    if (tid < 128)
        shf[SC_B / 4 + tid] = (which == 1) ? a_w[tid] * rsqrtf((float)kD) : 1.0f;
    __syncthreads();

    // Fragment address bases
    const uint32_t hA = sb + HB + (wm * 32 + (lane & 15)) * 272 + (lane >> 4) * 16;
    const uint32_t wBt = sb + WB + ((lane & 7) + 8 * ((lane >> 3) & 1)) * 272
                         + (wn * 64 + 8 * (lane >> 4)) * 2;

    float o[2][8][4];
#pragma unroll
    for (int mt = 0; mt < 2; mt++)
#pragma unroll
        for (int nt = 0; nt < 8; nt++)
#pragma unroll
            for (int q = 0; q < 4; q++) o[mt][nt][q] = 0.f;

#pragma unroll
    for (int ks = 0; ks < 8; ks++) {
        uint32_t a[2][4];
        ldsm4(a[0][0], a[0][1], a[0][2], a[0][3], hA + ks * 32);
        ldsm4(a[1][0], a[1][1], a[1][2], a[1][3], hA + 4352 + ks * 32);
#pragma unroll
        for (int ntp = 0; ntp < 4; ntp++) {
            uint32_t b0, b1, b2, b3;
            ldsm4t(b0, b1, b2, b3, wBt + ks * 4352 + ntp * 32);
            mma_f16(o[0][ntp * 2],     a[0], b0, b1);
            mma_f16(o[1][ntp * 2],     a[1], b0, b1);
            mma_f16(o[0][ntp * 2 + 1], a[0], b2, b3);
            mma_f16(o[1][ntp * 2 + 1], a[1], b2, b3);
        }
    }
    __syncthreads();

    // Scale + round to fp16, stage into H region, then coalesced 16B stores
#pragma unroll
    for (int mt = 0; mt < 2; mt++)
#pragma unroll
        for (int dd = 0; dd < 2; dd++) {
            const int r = wm * 32 + mt * 16 + g + 8 * dd;
#pragma unroll
            for (int nt = 0; nt < 8; nt++) {
                const int c0 = wn * 64 + nt * 8 + 2 * tig;
                const float cs0 = shf[SC_B / 4 + c0], cs1 = shf[SC_B / 4 + c0 + 1];
                *reinterpret_cast<__half2*>(smc + HB + (r * 136 + c0) * 2) =
                    __floats2half2_rn(o[mt][nt][2 * dd] * cs0,
                                      o[mt][nt][2 * dd + 1] * cs1);
            }
        }
    __syncthreads();
#pragma unroll
    for (int i = 0; i < 8; i++) {
        const int idx = tid + 256 * i;
        const int r = idx >> 4, c8 = (idx & 15) * 8;
        *reinterpret_cast<uint4*>(&outp[(size_t)(row0 + r) * kD + c8]) =
            *reinterpret_cast<const uint4*>(smc + HB + (r * 136 + c8) * 2);
    }
}

// ---------------------------------------------------------------------------
// Gate: sigmoid(op_emb @ op_W + op_b) (unchanged fp32, ~8us)
// ---------------------------------------------------------------------------
struct GateSmem {
    float W[64][129];
    float E[64][65];
    float bias[128];
};

__global__ void __launch_bounds__(256) gate_kernel(
    const float* __restrict__ op_emb,
    const float* __restrict__ op_W,
    const float* __restrict__ op_b)
{
    extern __shared__ char raw[];
    GateSmem& sm = *reinterpret_cast<GateSmem*>(raw);
    const int tid = threadIdx.x;
    const int row0 = blockIdx.x * 64;

    for (int i = tid; i < 64 * 128; i += 256) sm.W[i >> 7][i & 127] = op_W[i];
    for (int i = tid; i < 64 * 64; i += 256)
        sm.E[i >> 6][i & 63] = op_emb[(size_t)row0 * kOpe + i];
    if (tid < 128) sm.bias[tid] = op_b[tid];
    __syncthreads();

    const int tx = tid & 15, ty = tid >> 4;
    float acc[4][8];
#pragma unroll
    for (int i = 0; i < 4; i++)
#pragma unroll
        for (int j = 0; j < 8; j++) acc[i][j] = 0.f;

    const float* er[4];
#pragma unroll
    for (int i = 0; i < 4; i++) er[i] = sm.E[ty + 16 * i];

#pragma unroll 4
    for (int k = 0; k < 64; k++) {
        float a[4], b[8];
#pragma unroll
        for (int i = 0; i < 4; i++) a[i] = er[i][k];
#pragma unroll
        for (int j = 0; j < 8; j++) b[j] = sm.W[k][tx + 16 * j];
#pragma unroll
        for (int i = 0; i < 4; i++)
#pragma unroll
            for (int j = 0; j < 8; j++) acc[i][j] += a[i] * b[j];
    }

    float bb[8];
#pragma unroll
    for (int j = 0; j < 8; j++) bb[j] = sm.bias[tx + 16 * j];
    __syncthreads();
    float (*stage)[128] = reinterpret_cast<float(*)[128]>(raw);
#pragma unroll
    for (int i = 0; i < 4; i++)
#pragma unroll
        for (int j = 0; j < 8; j++) {
            float v = acc[i][j] + bb[j];
            stage[ty + 16 * i][tx + 16 * j] = 1.f / (1.f + __expf(-v));
        }
    __syncthreads();
    for (int i = tid; i < 64 * 128; i += 256)
        g_gate[(size_t)row0 * kD + i] = stage[i >> 7][i & 127];
}

// ---------------------------------------------------------------------------
// fp16 mma flash attention, cp.async pipelined, ldmatrix fragments.
//   S = Q K^T; P = exp(leaky(S)*adj) (no max shift, scores tiny);
//   O += P V^T across 32 tiles (fp32 register accum, no rescale);
//   epilogue: /rowsum, gate, LayerNorm.
// 8 warps 4(M)x2(N). K double-buffered; V consumed via ldmatrix.trans
// (no transpose needed anywhere). 3 barriers/tile.
// ---------------------------------------------------------------------------
__global__ void __launch_bounds__(256, 1) attn_kernel(
    const float* __restrict__ adj,
    const float* __restrict__ ln_g,
    const float* __restrict__ ln_b,
    float* __restrict__ out)
{
    extern __shared__ char smc[];
    float* const shf = reinterpret_cast<float*>(smc);
    const uint32_t sb = smem_u32(smc);
    const int tid  = threadIdx.x;
    const int lane = tid & 31, wid = tid >> 5;
    const int g    = lane >> 2, tig = lane & 3;
    const int wm   = wid & 3,  wn  = wid >> 2;
    const int b    = blockIdx.y;
    const int e0   = blockIdx.x * BE;

    // Prologue: async-copy Q (group) and K tile 0 (group)
    {
        const __half* __restrict__ qb = g_q + ((size_t)b * kN + e0) * kD;
#pragma unroll
        for (int i = 0; i < 8; i++) {
            const int idx = tid + 256 * i;
            const int r = idx >> 4, c8 = (idx & 15) * 8;
            cp16(sb + QB + r * 272 + c8 * 2, qb + r * kD + c8);
        }
        CP_COMMIT();
        const __half* __restrict__ kb = g_k + (size_t)b * kN * kD;
#pragma unroll
        for (int i = 0; i < 4; i++) {
            const int idx = tid + 256 * i;
            const int r = idx >> 4, c8 = (idx & 15) * 8;
            cp16(sb + K0B + r * 272 + c8 * 2, kb + r * kD + c8);
        }
        CP_COMMIT();
    }
    if (tid < 128) shf[tid] = 0.f;   // rowsum

    float o[2][8][4];
#pragma unroll
    for (int mt = 0; mt < 2; mt++)
#pragma unroll
        for (int nt = 0; nt < 8; nt++)
#pragma unroll
            for (int q = 0; q < 4; q++) o[mt][nt][q] = 0.f;
    float rsum[2][2] = {{0.f, 0.f}, {0.f, 0.f}};

    // Fragment address bases
    const uint32_t qA = sb + QB + (wm * 32 + (lane & 15)) * 272 + (lane >> 4) * 16;
    const uint32_t kBoff = (wn * 32 + (lane & 7) + 8 * (lane >> 4)) * 272
                           + ((lane >> 3) & 1) * 16;
    const uint32_t pA = sb + PB + (wm * 32 + (lane & 15)) * 144 + (lane >> 4) * 16;
    const uint32_t vBt = sb + VB + ((lane & 7) + 8 * ((lane >> 3) & 1)) * 272
                         + (wn * 64 + 8 * (lane >> 4)) * 2;

    const __half* __restrict__ k_base = g_k + (size_t)b * kN * kD;
    const __half* __restrict__ v_base = g_v + (size_t)b * kN * kD;

    for (int lt = 0; lt < NT; lt++) {
        __syncthreads();   // A: MMA2(t-1) done -> V, P buffers free

        // V(t) async copy (waited before MMA2)
        {
            const __half* __restrict__ vb = v_base + (size_t)lt * BL * kD;
#pragma unroll
            for (int i = 0; i < 4; i++) {
                const int idx = tid + 256 * i;
                const int r = idx >> 4, c8 = (idx & 15) * 8;
                cp16(sb + VB + r * 272 + c8 * 2, vb + r * kD + c8);
            }
            CP_COMMIT();
        }

        // adj tile prefetch -> registers (streaming; hidden under MMA1)
        float2 adjv[2][2][4];
        {
            const float* __restrict__ ab =
                adj + ((size_t)b * kN + e0) * kN + (size_t)lt * BL;
#pragma unroll
            for (int mt = 0; mt < 2; mt++)
#pragma unroll
                for (int dd = 0; dd < 2; dd++) {
                    const int r = wm * 32 + mt * 16 + g + 8 * dd;
                    const float* ap = ab + (size_t)r * kN + wn * 32 + 2 * tig;
#pragma unroll
                    for (int nt = 0; nt < 4; nt++)
                        adjv[mt][dd][nt] =
                            __ldcs(reinterpret_cast<const float2*>(ap + nt * 8));
                }
        }

        CP_WAIT1();        // K(t) (and Q on first iter) arrived
        __syncthreads();   // B: everyone's K copies visible

        // MMA1: S = Q K^T  (128 x 64)
        const uint32_t kbuf = sb + ((lt & 1) ? K1B : K0B) + kBoff;
        float s[2][4][4];
#pragma unroll
        for (int mt = 0; mt < 2; mt++)
#pragma unroll
            for (int nt = 0; nt < 4; nt++)
#pragma unroll
                for (int q = 0; q < 4; q++) s[mt][nt][q] = 0.f;
#pragma unroll
        for (int ks = 0; ks < 8; ks++) {
            uint32_t a[2][4];
            ldsm4(a[0][0], a[0][1], a[0][2], a[0][3], qA + ks * 32);
            ldsm4(a[1][0], a[1][1], a[1][2], a[1][3], qA + 4352 + ks * 32);
#pragma unroll
            for (int ntp = 0; ntp < 2; ntp++) {
                uint32_t b0, b1, b2, b3;
                ldsm4(b0, b1, b2, b3, kbuf + ntp * 4352 + ks * 32);
                mma_f16(s[0][ntp * 2],     a[0], b0, b1);
                mma_f16(s[1][ntp * 2],     a[1], b0, b1);
                mma_f16(s[0][ntp * 2 + 1], a[0], b2, b3);
                mma_f16(s[1][ntp * 2 + 1], a[1], b2, b3);
            }
        }

        // K(t+1) async copy into the other buffer (no barrier needed: that
        // buffer's last readers finished before barrier B of this tile)
        {
            const int tn = (lt + 1) & (NT - 1);
            const __half* __restrict__ kbn = k_base + (size_t)tn * BL * kD;
            const uint32_t kdst = sb + ((lt & 1) ? K0B : K1B);
#pragma unroll
            for (int i = 0; i < 4; i++) {
                const int idx = tid + 256 * i;
                const int r = idx >> 4, c8 = (idx & 15) * 8;
                cp16(kdst + r * 272 + c8 * 2, kbn + r * kD + c8);
            }
            CP_COMMIT();
        }

        // P = exp(leaky(S) * adj) -> P buffer (fp16); rowsum in regs
#pragma unroll
        for (int mt = 0; mt < 2; mt++)
#pragma unroll
            for (int dd = 0; dd < 2; dd++) {
                const int r = wm * 32 + mt * 16 + g + 8 * dd;
#pragma unroll
                for (int nt = 0; nt < 4; nt++) {
                    float v0 = s[mt][nt][2 * dd + 0];
                    float v1 = s[mt][nt][2 * dd + 1];
                    v0 = fmaxf(v0, 0.2f * v0);     // leaky_relu(0.2)
                    v1 = fmaxf(v1, 0.2f * v1);
                    const float2 av = adjv[mt][dd][nt];
                    const float p0 = __expf(v0 * av.x);
                    const float p1 = __expf(v1 * av.y);
                    rsum[mt][dd] += p0 + p1;
                    const int c0 = wn * 32 + nt * 8 + 2 * tig;
                    *reinterpret_cast<__half2*>(smc + PB + (r * 72 + c0) * 2) =
                        __floats2half2_rn(p0, p1);
                }
            }

        CP_WAIT1();        // V(t) arrived (K(t+1) still in flight)
        __syncthreads();   // D: P + everyone's V visible

        // MMA2: O += P V^T  (128 x 128)
#pragma unroll
        for (int ks = 0; ks < 4; ks++) {
            uint32_t a[2][4];
            ldsm4(a[0][0], a[0][1], a[0][2], a[0][3], pA + ks * 32);
            ldsm4(a[1][0], a[1][1], a[1][2], a[1][3], pA + 2304 + ks * 32);
#pragma unroll
            for (int ntp = 0; ntp < 4; ntp++) {
                uint32_t b0, b1, b2, b3;
                ldsm4t(b0, b1, b2, b3, vBt + ks * 4352 + ntp * 32);
                mma_f16(o[0][ntp * 2],     a[0], b0, b1);
                mma_f16(o[1][ntp * 2],     a[1], b0, b1);
                mma_f16(o[0][ntp * 2 + 1], a[0], b2, b3);
                mma_f16(o[1][ntp * 2 + 1], a[1], b2, b3);
            }
        }
    }

    __syncthreads();
    // Rowsum reduction: 4 lanes (tig) share each row; wn pair via atomicAdd
#pragma unroll
    for (int mt = 0; mt < 2; mt++)
#pragma unroll
        for (int dd = 0; dd < 2; dd++) {
            float v = rsum[mt][dd];
            v += __shfl_xor_sync(0xffffffffu, v, 1);
            v += __shfl_xor_sync(0xffffffffu, v, 2);
            if (tig == 0)
                atomicAdd(&shf[wm * 32 + mt * 16 + g + 8 * dd], v);
        }
    // Stage O (fp32) into dead Q/K smem (float base 128, stride 132)
#pragma unroll
    for (int mt = 0; mt < 2; mt++)
#pragma unroll
        for (int dd = 0; dd < 2; dd++) {
            const int r = wm * 32 + mt * 16 + g + 8 * dd;
#pragma unroll
            for (int nt = 0; nt < 8; nt++) {
                const int c0 = wn * 64 + nt * 8 + 2 * tig;
                *reinterpret_cast<float2*>(&shf[128 + r * 132 + c0]) =
                    make_float2(o[mt][nt][2 * dd], o[mt][nt][2 * dd + 1]);
            }
        }
    __syncthreads();

    // Fused /rowsum + gate + LayerNorm epilogue: warp per 16 rows, float4
    const float4 lg = *reinterpret_cast<const float4*>(&ln_g[lane * 4]);
    const float4 lb = *reinterpret_cast<const float4*>(&ln_b[lane * 4]);
#pragma unroll 2
    for (int rr = 0; rr < 16; rr++) {
        const int r = wid * 16 + rr;
        const float inv = 1.f / shf[r];
        const float4 ov = *reinterpret_cast<float4*>(&shf[128 + r * 132 + lane * 4]);
        const size_t gidx = ((size_t)b * kN + e0 + r) * kD + lane * 4;
        const float4 gv = *reinterpret_cast<const float4*>(&g_gate[gidx]);
        const float h0 = ov.x * inv * gv.x, h1 = ov.y * inv * gv.y;
        const float h2 = ov.z * inv * gv.z, h3 = ov.w * inv * gv.w;
        float sum = h0 + h1 + h2 + h3;
#pragma unroll
        for (int off = 16; off; off >>= 1) sum += __shfl_xor_sync(0xffffffffu, sum, off);
        const float mu = sum * (1.f / 128.f);
        const float d0 = h0 - mu, d1 = h1 - mu, d2 = h2 - mu, d3 = h3 - mu;
        float vs = d0 * d0 + d1 * d1 + d2 * d2 + d3 * d3;
#pragma unroll
        for (int off = 16; off; off >>= 1) vs += __shfl_xor_sync(0xffffffffu, vs, off);
        const float rstd = rsqrtf(vs * (1.f / 128.f) + 1e-5f);
        float4 res;
        res.x = d0 * rstd * lg.x + lb.x;
        res.y = d1 * rstd * lg.y + lb.y;
        res.z = d2 * rstd * lg.z + lb.z;
        res.w = d3 * rstd * lg.w + lb.w;
        *reinterpret_cast<float4*>(&out[gidx]) = res;
    }
}

// ---------------------------------------------------------------------------
// Launch
// ---------------------------------------------------------------------------
extern "C" void kernel_launch(void* const* d_in, const int* in_sizes, int n_in,
                              void* d_out, int out_size)
{
    const float* h    = (const float*)d_in[0];
    const float* adj  = (const float*)d_in[1];
    const float* op_e = (const float*)d_in[2];
    const float* Wk   = (const float*)d_in[3];
    const float* Wq   = (const float*)d_in[4];
    const float* Wv   = (const float*)d_in[5];
    const float* a_w  = (const float*)d_in[6];
    const float* op_W = (const float*)d_in[7];
    const float* op_b = (const float*)d_in[8];
    const float* ln_g = (const float*)d_in[9];
    const float* ln_b = (const float*)d_in[10];
    float* out = (float*)d_out;

    cudaFuncSetAttribute(proj_kernel, cudaFuncAttributeMaxDynamicSharedMemorySize,
                         PROJ_BYTES);
    cudaFuncSetAttribute(gate_kernel, cudaFuncAttributeMaxDynamicSharedMemorySize,
                         (int)sizeof(GateSmem));
    cudaFuncSetAttribute(attn_kernel, cudaFuncAttributeMaxDynamicSharedMemorySize,
                         ATTN_BYTES);

    proj_kernel<<<dim3((kB * kN) / 128, 3), 256, PROJ_BYTES>>>(h, Wq, Wk, Wv, a_w);
    gate_kernel<<<(kB * kN) / 64, 256, sizeof(GateSmem)>>>(op_e, op_W, op_b);
    attn_kernel<<<dim3(kN / BE, kB), 256, ATTN_BYTES>>>(adj, ln_g, ln_b, out);
}

// round 10
// speedup vs baseline: 1.6652x; 1.0015x over previous
#include <cuda_runtime.h>
#include <cuda_fp16.h>
#include <cstdint>

// Problem constants
namespace {
constexpr int kB   = 16;
constexpr int kN   = 2048;
constexpr int kD   = 128;
constexpr int kOpe = 64;
constexpr int BE   = 128;          // e-rows per attention CTA
constexpr int BL   = 64;           // l-cols per tile
constexpr int NT   = kN / BL;      // 32 tiles

// attention smem byte offsets (half rows stride 136 halves = 272 B = 17x16B)
constexpr int RS_B = 0;                       // rowsum[128] f32
constexpr int QB   = 512;                     // Q fp16 [128][136]
constexpr int K0B  = QB  + 128 * 272;         // K fp16 [64][136] buf0
constexpr int K1B  = K0B + 64 * 272;          // K buf1
constexpr int VB   = K1B + 64 * 272;          // V fp16 [64][136]
constexpr int PB   = VB  + 64 * 272;          // P fp16 [128][72]
constexpr int ATTN_BYTES = PB + 128 * 144;    // 105984

// proj smem byte offsets
constexpr int HB   = 0;                       // H fp16 [128][136]; reused as out stage
constexpr int WB   = 128 * 272;               // W fp16 [128][136] (natural [k][n])
constexpr int SC_B = WB + 128 * 272;          // scale[128] f32
constexpr int PROJ_BYTES = SC_B + 512;        // 70144
}

// Scratch (allocation-free rule: __device__ globals), fp16
__device__ __half g_q[kB * kN * kD];
__device__ __half g_k[kB * kN * kD];     // (h@Wk) * a_w / sqrt(d) folded in
__device__ __half g_v[kB * kN * kD];
__device__ float  g_gate[kB * kN * kD];

// ---------------------------------------------------------------------------
// PTX helpers
// ---------------------------------------------------------------------------
__device__ __forceinline__ uint32_t smem_u32(const void* p) {
    uint32_t a;
    asm("{ .reg .u64 t; cvta.to.shared.u64 t, %1; cvt.u32.u64 %0, t; }"
        : "=r"(a) : "l"(p));
    return a;
}
__device__ __forceinline__ void ldsm4(uint32_t& r0, uint32_t& r1, uint32_t& r2,
                                      uint32_t& r3, uint32_t addr) {
    asm volatile("ldmatrix.sync.aligned.m8n8.x4.shared.b16 {%0,%1,%2,%3}, [%4];"
                 : "=r"(r0), "=r"(r1), "=r"(r2), "=r"(r3) : "r"(addr));
}
__device__ __forceinline__ void ldsm4t(uint32_t& r0, uint32_t& r1, uint32_t& r2,
                                       uint32_t& r3, uint32_t addr) {
    asm volatile("ldmatrix.sync.aligned.m8n8.x4.trans.shared.b16 {%0,%1,%2,%3}, [%4];"
                 : "=r"(r0), "=r"(r1), "=r"(r2), "=r"(r3) : "r"(addr));
}
// C += A(16x16) * B(16x8), fp16 inputs, fp32 accum
__device__ __forceinline__ void mma_f16(float* c, const uint32_t* a,
                                        uint32_t b0, uint32_t b1) {
    asm volatile(
        "mma.sync.aligned.m16n8k16.row.col.f32.f16.f16.f32 "
        "{%0,%1,%2,%3}, {%4,%5,%6,%7}, {%8,%9}, {%0,%1,%2,%3};"
        : "+f"(c[0]), "+f"(c[1]), "+f"(c[2]), "+f"(c[3])
        : "r"(a[0]), "r"(a[1]), "r"(a[2]), "r"(a[3]), "r"(b0), "r"(b1));
}
__device__ __forceinline__ void cp16(uint32_t dst, const void* src) {
    asm volatile("cp.async.cg.shared.global [%0], [%1], 16;"
                 :: "r"(dst), "l"(src) : "memory");
}
#define CP_COMMIT() asm volatile("cp.async.commit_group;" ::: "memory")
#define CP_WAIT1()  asm volatile("cp.async.wait_group 1;" ::: "memory")
#define CP_WAIT0()  asm volatile("cp.async.wait_group 0;" ::: "memory")

// ---------------------------------------------------------------------------
// QKV projection via fp16 mma: out = h @ W (which: 0=Q,1=K,2=V), fp16 out.
// K gets a_w/sqrt(d) folded in (applied in fp32 before rounding).
// W consumed in natural [k][n] layout via ldmatrix.trans. 8 warps 4(M)x2(N).
// ---------------------------------------------------------------------------
__global__ void __launch_bounds__(256, 2) proj_kernel(
    const float* __restrict__ h,
    const float* __restrict__ Wq,
    const float* __restrict__ Wk,
    const float* __restrict__ Wv,
    const float* __restrict__ a_w)
{
    extern __shared__ char smc[];
    float* const shf = reinterpret_cast<float*>(smc);
    const uint32_t sb = smem_u32(smc);
    const int tid  = threadIdx.x;
    const int lane = tid & 31, wid = tid >> 5;
    const int g    = lane >> 2, tig = lane & 3;
    const int wm   = wid & 3,  wn  = wid >> 2;
    const int which = blockIdx.y;
    const float* __restrict__ W = (which == 0) ? Wq : (which == 1) ? Wk : Wv;
    __half* __restrict__ outp = (which == 0) ? g_q : (which == 1) ? g_k : g_v;
    const int row0 = blockIdx.x * 128;

    // Stage H and W as fp16 (stride 136 halves)
    {
        const float* __restrict__ hb = h + (size_t)row0 * kD;
#pragma unroll
        for (int i = 0; i < 16; i++) {
            const int idx = tid + 256 * i;
            const int r = idx >> 5, c4 = (idx & 31) << 2;
            const float4 v = *reinterpret_cast<const float4*>(&hb[r * kD + c4]);
            *reinterpret_cast<__half2*>(smc + HB + (r * 136 + c4) * 2) =
                __floats2half2_rn(v.x, v.y);
            *reinterpret_cast<__half2*>(smc + HB + (r * 136 + c4) * 2 + 4) =
                __floats2half2_rn(v.z, v.w);
            const float4 w = *reinterpret_cast<const float4*>(&W[r * kD + c4]);
            *reinterpret_cast<__half2*>(smc + WB + (r * 136 + c4) * 2) =
                __floats2half2_rn(w.x, w.y);
            *reinterpret_cast<__half2*>(smc + WB + (r * 136 + c4) * 2 + 4) =
                __floats2half2_rn(w.z, w.w);
        }
    }
    if (tid < 128)
        shf[SC_B / 4 + tid] = (which == 1) ? a_w[tid] * rsqrtf((float)kD) : 1.0f;
    __syncthreads();

    // Fragment address bases
    const uint32_t hA = sb + HB + (wm * 32 + (lane & 15)) * 272 + (lane >> 4) * 16;
    const uint32_t wBt = sb + WB + ((lane & 7) + 8 * ((lane >> 3) & 1)) * 272
                         + (wn * 64 + 8 * (lane >> 4)) * 2;

    float o[2][8][4];
#pragma unroll
    for (int mt = 0; mt < 2; mt++)
#pragma unroll
        for (int nt = 0; nt < 8; nt++)
#pragma unroll
            for (int q = 0; q < 4; q++) o[mt][nt][q] = 0.f;

#pragma unroll
    for (int ks = 0; ks < 8; ks++) {
        uint32_t a[2][4];
        ldsm4(a[0][0], a[0][1], a[0][2], a[0][3], hA + ks * 32);
        ldsm4(a[1][0], a[1][1], a[1][2], a[1][3], hA + 4352 + ks * 32);
#pragma unroll
        for (int ntp = 0; ntp < 4; ntp++) {
            uint32_t b0, b1, b2, b3;
            ldsm4t(b0, b1, b2, b3, wBt + ks * 4352 + ntp * 32);
            mma_f16(o[0][ntp * 2],     a[0], b0, b1);
            mma_f16(o[1][ntp * 2],     a[1], b0, b1);
            mma_f16(o[0][ntp * 2 + 1], a[0], b2, b3);
            mma_f16(o[1][ntp * 2 + 1], a[1], b2, b3);
        }
    }
    __syncthreads();

    // Scale + round to fp16, stage into H region, then coalesced 16B stores
#pragma unroll
    for (int mt = 0; mt < 2; mt++)
#pragma unroll
        for (int dd = 0; dd < 2; dd++) {
            const int r = wm * 32 + mt * 16 + g + 8 * dd;
#pragma unroll
            for (int nt = 0; nt < 8; nt++) {
                const int c0 = wn * 64 + nt * 8 + 2 * tig;
                const float cs0 = shf[SC_B / 4 + c0], cs1 = shf[SC_B / 4 + c0 + 1];
                *reinterpret_cast<__half2*>(smc + HB + (r * 136 + c0) * 2) =
                    __floats2half2_rn(o[mt][nt][2 * dd] * cs0,
                                      o[mt][nt][2 * dd + 1] * cs1);
            }
        }
    __syncthreads();
#pragma unroll
    for (int i = 0; i < 8; i++) {
        const int idx = tid + 256 * i;
        const int r = idx >> 4, c8 = (idx & 15) * 8;
        *reinterpret_cast<uint4*>(&outp[(size_t)(row0 + r) * kD + c8]) =
            *reinterpret_cast<const uint4*>(smc + HB + (r * 136 + c8) * 2);
    }
}

// ---------------------------------------------------------------------------
// Gate: sigmoid(op_emb @ op_W + op_b) (unchanged fp32, ~8us)
// ---------------------------------------------------------------------------
struct GateSmem {
    float W[64][129];
    float E[64][65];
    float bias[128];
};

__global__ void __launch_bounds__(256) gate_kernel(
    const float* __restrict__ op_emb,
    const float* __restrict__ op_W,
    const float* __restrict__ op_b)
{
    extern __shared__ char raw[];
    GateSmem& sm = *reinterpret_cast<GateSmem*>(raw);
    const int tid = threadIdx.x;
    const int row0 = blockIdx.x * 64;

    for (int i = tid; i < 64 * 128; i += 256) sm.W[i >> 7][i & 127] = op_W[i];
    for (int i = tid; i < 64 * 64; i += 256)
        sm.E[i >> 6][i & 63] = op_emb[(size_t)row0 * kOpe + i];
    if (tid < 128) sm.bias[tid] = op_b[tid];
    __syncthreads();

    const int tx = tid & 15, ty = tid >> 4;
    float acc[4][8];
#pragma unroll
    for (int i = 0; i < 4; i++)
#pragma unroll
        for (int j = 0; j < 8; j++) acc[i][j] = 0.f;

    const float* er[4];
#pragma unroll
    for (int i = 0; i < 4; i++) er[i] = sm.E[ty + 16 * i];

#pragma unroll 4
    for (int k = 0; k < 64; k++) {
        float a[4], b[8];
#pragma unroll
        for (int i = 0; i < 4; i++) a[i] = er[i][k];
#pragma unroll
        for (int j = 0; j < 8; j++) b[j] = sm.W[k][tx + 16 * j];
#pragma unroll
        for (int i = 0; i < 4; i++)
#pragma unroll
            for (int j = 0; j < 8; j++) acc[i][j] += a[i] * b[j];
    }

    float bb[8];
#pragma unroll
    for (int j = 0; j < 8; j++) bb[j] = sm.bias[tx + 16 * j];
    __syncthreads();
    float (*stage)[128] = reinterpret_cast<float(*)[128]>(raw);
#pragma unroll
    for (int i = 0; i < 4; i++)
#pragma unroll
        for (int j = 0; j < 8; j++) {
            float v = acc[i][j] + bb[j];
            stage[ty + 16 * i][tx + 16 * j] = 1.f / (1.f + __expf(-v));
        }
    __syncthreads();
    for (int i = tid; i < 64 * 128; i += 256)
        g_gate[(size_t)row0 * kD + i] = stage[i >> 7][i & 127];
}

// ---------------------------------------------------------------------------
// fp16 mma flash attention, cp.async pipelined, ldmatrix fragments.
//   S = Q K^T; P = exp(leaky(S)*adj) (no max shift, scores tiny);
//   O += P V^T across 32 tiles (fp32 register accum, no rescale);
//   epilogue: /rowsum, gate, LayerNorm.
// 8 warps 4(M)x2(N). K double-buffered; V consumed via ldmatrix.trans
// (no transpose needed anywhere). 3 barriers/tile.
// ---------------------------------------------------------------------------
__global__ void __launch_bounds__(256, 1) attn_kernel(
    const float* __restrict__ adj,
    const float* __restrict__ ln_g,
    const float* __restrict__ ln_b,
    float* __restrict__ out)
{
    extern __shared__ char smc[];
    float* const shf = reinterpret_cast<float*>(smc);
    const uint32_t sb = smem_u32(smc);
    const int tid  = threadIdx.x;
    const int lane = tid & 31, wid = tid >> 5;
    const int g    = lane >> 2, tig = lane & 3;
    const int wm   = wid & 3,  wn  = wid >> 2;
    const int b    = blockIdx.y;
    const int e0   = blockIdx.x * BE;

    // Prologue: async-copy Q (group) and K tile 0 (group)
    {
        const __half* __restrict__ qb = g_q + ((size_t)b * kN + e0) * kD;
#pragma unroll
        for (int i = 0; i < 8; i++) {
            const int idx = tid + 256 * i;
            const int r = idx >> 4, c8 = (idx & 15) * 8;
            cp16(sb + QB + r * 272 + c8 * 2, qb + r * kD + c8);
        }
        CP_COMMIT();
        const __half* __restrict__ kb = g_k + (size_t)b * kN * kD;
#pragma unroll
        for (int i = 0; i < 4; i++) {
            const int idx = tid + 256 * i;
            const int r = idx >> 4, c8 = (idx & 15) * 8;
            cp16(sb + K0B + r * 272 + c8 * 2, kb + r * kD + c8);
        }
        CP_COMMIT();
    }
    if (tid < 128) shf[tid] = 0.f;   // rowsum

    float o[2][8][4];
#pragma unroll
    for (int mt = 0; mt < 2; mt++)
#pragma unroll
        for (int nt = 0; nt < 8; nt++)
#pragma unroll
            for (int q = 0; q < 4; q++) o[mt][nt][q] = 0.f;
    float rsum[2][2] = {{0.f, 0.f}, {0.f, 0.f}};

    // Fragment address bases
    const uint32_t qA = sb + QB + (wm * 32 + (lane & 15)) * 272 + (lane >> 4) * 16;
    const uint32_t kBoff = (wn * 32 + (lane & 7) + 8 * (lane >> 4)) * 272
                           + ((lane >> 3) & 1) * 16;
    const uint32_t pA = sb + PB + (wm * 32 + (lane & 15)) * 144 + (lane >> 4) * 16;
    const uint32_t vBt = sb + VB + ((lane & 7) + 8 * ((lane >> 3) & 1)) * 272
                         + (wn * 64 + 8 * (lane >> 4)) * 2;

    const __half* __restrict__ k_base = g_k + (size_t)b * kN * kD;
    const __half* __restrict__ v_base = g_v + (size_t)b * kN * kD;

    for (int lt = 0; lt < NT; lt++) {
        __syncthreads();   // A: MMA2(t-1) done -> V, P buffers free

        // V(t) async copy (waited before MMA2)
        {
            const __half* __restrict__ vb = v_base + (size_t)lt * BL * kD;
#pragma unroll
            for (int i = 0; i < 4; i++) {
                const int idx = tid + 256 * i;
                const int r = idx >> 4, c8 = (idx & 15) * 8;
                cp16(sb + VB + r * 272 + c8 * 2, vb + r * kD + c8);
            }
            CP_COMMIT();
        }

        // adj tile prefetch -> registers (streaming; hidden under MMA1)
        float2 adjv[2][2][4];
        {
            const float* __restrict__ ab =
                adj + ((size_t)b * kN + e0) * kN + (size_t)lt * BL;
#pragma unroll
            for (int mt = 0; mt < 2; mt++)
#pragma unroll
                for (int dd = 0; dd < 2; dd++) {
                    const int r = wm * 32 + mt * 16 + g + 8 * dd;
                    const float* ap = ab + (size_t)r * kN + wn * 32 + 2 * tig;
#pragma unroll
                    for (int nt = 0; nt < 4; nt++)
                        adjv[mt][dd][nt] =
                            __ldcs(reinterpret_cast<const float2*>(ap + nt * 8));
                }
        }

        CP_WAIT1();        // K(t) (and Q on first iter) arrived
        __syncthreads();   // B: everyone's K copies visible

        // MMA1: S = Q K^T  (128 x 64)
        const uint32_t kbuf = sb + ((lt & 1) ? K1B : K0B) + kBoff;
        float s[2][4][4];
#pragma unroll
        for (int mt = 0; mt < 2; mt++)
#pragma unroll
            for (int nt = 0; nt < 4; nt++)
#pragma unroll
                for (int q = 0; q < 4; q++) s[mt][nt][q] = 0.f;
#pragma unroll
        for (int ks = 0; ks < 8; ks++) {
            uint32_t a[2][4];
            ldsm4(a[0][0], a[0][1], a[0][2], a[0][3], qA + ks * 32);
            ldsm4(a[1][0], a[1][1], a[1][2], a[1][3], qA + 4352 + ks * 32);
#pragma unroll
            for (int ntp = 0; ntp < 2; ntp++) {
                uint32_t b0, b1, b2, b3;
                ldsm4(b0, b1, b2, b3, kbuf + ntp * 4352 + ks * 32);
                mma_f16(s[0][ntp * 2],     a[0], b0, b1);
                mma_f16(s[1][ntp * 2],     a[1], b0, b1);
                mma_f16(s[0][ntp * 2 + 1], a[0], b2, b3);
                mma_f16(s[1][ntp * 2 + 1], a[1], b2, b3);
            }
        }

        // K(t+1) async copy into the other buffer (no barrier needed: that
        // buffer's last readers finished before barrier B of this tile)
        {
            const int tn = (lt + 1) & (NT - 1);
            const __half* __restrict__ kbn = k_base + (size_t)tn * BL * kD;
            const uint32_t kdst = sb + ((lt & 1) ? K0B : K1B);
#pragma unroll
            for (int i = 0; i < 4; i++) {
                const int idx = tid + 256 * i;
                const int r = idx >> 4, c8 = (idx & 15) * 8;
                cp16(kdst + r * 272 + c8 * 2, kbn + r * kD + c8);
            }
            CP_COMMIT();
        }

        // P = exp(leaky(S) * adj) -> P buffer (fp16); rowsum in regs
#pragma unroll
        for (int mt = 0; mt < 2; mt++)
#pragma unroll
            for (int dd = 0; dd < 2; dd++) {
                const int r = wm * 32 + mt * 16 + g + 8 * dd;
#pragma unroll
                for (int nt = 0; nt < 4; nt++) {
                    float v0 = s[mt][nt][2 * dd + 0];
                    float v1 = s[mt][nt][2 * dd + 1];
                    v0 = fmaxf(v0, 0.2f * v0);     // leaky_relu(0.2)
                    v1 = fmaxf(v1, 0.2f * v1);
                    const float2 av = adjv[mt][dd][nt];
                    const float p0 = __expf(v0 * av.x);
                    const float p1 = __expf(v1 * av.y);
                    rsum[mt][dd] += p0 + p1;
                    const int c0 = wn * 32 + nt * 8 + 2 * tig;
                    *reinterpret_cast<__half2*>(smc + PB + (r * 72 + c0) * 2) =
                        __floats2half2_rn(p0, p1);
                }
            }

        CP_WAIT1();        // V(t) arrived (K(t+1) still in flight)
        __syncthreads();   // D: P + everyone's V visible

        // MMA2: O += P V^T  (128 x 128)
#pragma unroll
        for (int ks = 0; ks < 4; ks++) {
            uint32_t a[2][4];
            ldsm4(a[0][0], a[0][1], a[0][2], a[0][3], pA + ks * 32);
            ldsm4(a[1][0], a[1][1], a[1][2], a[1][3], pA + 2304 + ks * 32);
#pragma unroll
            for (int ntp = 0; ntp < 4; ntp++) {
                uint32_t b0, b1, b2, b3;
                ldsm4t(b0, b1, b2, b3, vBt + ks * 4352 + ntp * 32);
                mma_f16(o[0][ntp * 2],     a[0], b0, b1);
                mma_f16(o[1][ntp * 2],     a[1], b0, b1);
                mma_f16(o[0][ntp * 2 + 1], a[0], b2, b3);
                mma_f16(o[1][ntp * 2 + 1], a[1], b2, b3);
            }
        }
    }

    __syncthreads();
    // Rowsum reduction: 4 lanes (tig) share each row; wn pair via atomicAdd
#pragma unroll
    for (int mt = 0; mt < 2; mt++)
#pragma unroll
        for (int dd = 0; dd < 2; dd++) {
            float v = rsum[mt][dd];
            v += __shfl_xor_sync(0xffffffffu, v, 1);
            v += __shfl_xor_sync(0xffffffffu, v, 2);
            if (tig == 0)
                atomicAdd(&shf[wm * 32 + mt * 16 + g + 8 * dd], v);
        }
    // Stage O (fp32) into dead Q/K smem (float base 128, stride 132)
#pragma unroll
    for (int mt = 0; mt < 2; mt++)
#pragma unroll
        for (int dd = 0; dd < 2; dd++) {
            const int r = wm * 32 + mt * 16 + g + 8 * dd;
#pragma unroll
            for (int nt = 0; nt < 8; nt++) {
                const int c0 = wn * 64 + nt * 8 + 2 * tig;
                *reinterpret_cast<float2*>(&shf[128 + r * 132 + c0]) =
                    make_float2(o[mt][nt][2 * dd], o[mt][nt][2 * dd + 1]);
            }
        }
    __syncthreads();

    // Fused /rowsum + gate + LayerNorm epilogue: warp per 16 rows, float4
    const float4 lg = *reinterpret_cast<const float4*>(&ln_g[lane * 4]);
    const float4 lb = *reinterpret_cast<const float4*>(&ln_b[lane * 4]);
#pragma unroll 2
    for (int rr = 0; rr < 16; rr++) {
        const int r = wid * 16 + rr;
        const float inv = 1.f / shf[r];
        const float4 ov = *reinterpret_cast<float4*>(&shf[128 + r * 132 + lane * 4]);
        const size_t gidx = ((size_t)b * kN + e0 + r) * kD + lane * 4;
        const float4 gv = *reinterpret_cast<const float4*>(&g_gate[gidx]);
        const float h0 = ov.x * inv * gv.x, h1 = ov.y * inv * gv.y;
        const float h2 = ov.z * inv * gv.z, h3 = ov.w * inv * gv.w;
        float sum = h0 + h1 + h2 + h3;
#pragma unroll
        for (int off = 16; off; off >>= 1) sum += __shfl_xor_sync(0xffffffffu, sum, off);
        const float mu = sum * (1.f / 128.f);
        const float d0 = h0 - mu, d1 = h1 - mu, d2 = h2 - mu, d3 = h3 - mu;
        float vs = d0 * d0 + d1 * d1 + d2 * d2 + d3 * d3;
#pragma unroll
        for (int off = 16; off; off >>= 1) vs += __shfl_xor_sync(0xffffffffu, vs, off);
        const float rstd = rsqrtf(vs * (1.f / 128.f) + 1e-5f);
        float4 res;
        res.x = d0 * rstd * lg.x + lb.x;
        res.y = d1 * rstd * lg.y + lb.y;
        res.z = d2 * rstd * lg.z + lb.z;
        res.w = d3 * rstd * lg.w + lb.w;
        *reinterpret_cast<float4*>(&out[gidx]) = res;
    }
}

// ---------------------------------------------------------------------------
// Launch
// ---------------------------------------------------------------------------
extern "C" void kernel_launch(void* const* d_in, const int* in_sizes, int n_in,
                              void* d_out, int out_size)
{
    const float* h    = (const float*)d_in[0];
    const float* adj  = (const float*)d_in[1];
    const float* op_e = (const float*)d_in[2];
    const float* Wk   = (const float*)d_in[3];
    const float* Wq   = (const float*)d_in[4];
    const float* Wv   = (const float*)d_in[5];
    const float* a_w  = (const float*)d_in[6];
    const float* op_W = (const float*)d_in[7];
    const float* op_b = (const float*)d_in[8];
    const float* ln_g = (const float*)d_in[9];
    const float* ln_b = (const float*)d_in[10];
    float* out = (float*)d_out;

    cudaFuncSetAttribute(proj_kernel, cudaFuncAttributeMaxDynamicSharedMemorySize,
                         PROJ_BYTES);
    cudaFuncSetAttribute(gate_kernel, cudaFuncAttributeMaxDynamicSharedMemorySize,
                         (int)sizeof(GateSmem));
    cudaFuncSetAttribute(attn_kernel, cudaFuncAttributeMaxDynamicSharedMemorySize,
                         ATTN_BYTES);

    proj_kernel<<<dim3((kB * kN) / 128, 3), 256, PROJ_BYTES>>>(h, Wq, Wk, Wv, a_w);
    gate_kernel<<<(kB * kN) / 64, 256, sizeof(GateSmem)>>>(op_e, op_W, op_b);
    attn_kernel<<<dim3(kN / BE, kB), 256, ATTN_BYTES>>>(adj, ln_g, ln_b, out);
}